// round 3
// baseline (speedup 1.0000x reference)
#include <cuda_runtime.h>

#define RKHS 20
#define OUTD 128

// One warp per row. Lane l owns output columns [4l, 4l+4).
// W_proj/b_proj/W_fb/b_fb are hoisted into registers (row-invariant).
// KDE gather is warp-uniform -> broadcast LDG.128 x5.
// Store: one STG.128 per lane, 512B contiguous per warp.
// kde_mask arrives as int32 (harness coerces jax bool -> int32).
__global__ __launch_bounds__(256) void kde_time_encoder_kernel(
    const float* __restrict__ t_diff,
    const int* __restrict__ kde_idx,
    const int* __restrict__ kde_mask,
    const float* __restrict__ kde_table,
    const float* __restrict__ W_proj,
    const float* __restrict__ b_proj,
    const float* __restrict__ W_fb,
    const float* __restrict__ b_fb,
    float* __restrict__ out,
    int n)
{
    const int lane = threadIdx.x & 31;
    const int obase = lane * 4;

    // Hoist per-lane weight slice into registers.
    float w[4][RKHS];
    float bp[4], wf[4], bf[4];
#pragma unroll
    for (int j = 0; j < 4; j++) {
        // (obase+j)*RKHS*4 bytes = o*80 bytes -> 16B aligned, float4 OK
        const float4* wrow = reinterpret_cast<const float4*>(W_proj + (obase + j) * RKHS);
#pragma unroll
        for (int q = 0; q < 5; q++) {
            float4 v = wrow[q];
            w[j][q * 4 + 0] = v.x;
            w[j][q * 4 + 1] = v.y;
            w[j][q * 4 + 2] = v.z;
            w[j][q * 4 + 3] = v.w;
        }
        bp[j] = b_proj[obase + j];
        wf[j] = W_fb[obase + j];
        bf[j] = b_fb[obase + j];
    }

    const int warp_global = (blockIdx.x * blockDim.x + threadIdx.x) >> 5;
    const int nwarps = (gridDim.x * blockDim.x) >> 5;

    for (int row = warp_global; row < n; row += nwarps) {
        float4 res;
        if (kde_mask[row] != 0) {
            // idx*RKHS*4 bytes = idx*80 -> 16B aligned
            const float4* kv = reinterpret_cast<const float4*>(
                kde_table + (size_t)kde_idx[row] * RKHS);
            float k[RKHS];
#pragma unroll
            for (int q = 0; q < 5; q++) {
                float4 v = kv[q];  // warp-uniform address -> L1 broadcast
                k[q * 4 + 0] = v.x;
                k[q * 4 + 1] = v.y;
                k[q * 4 + 2] = v.z;
                k[q * 4 + 3] = v.w;
            }
            float a0 = bp[0], a1 = bp[1], a2 = bp[2], a3 = bp[3];
#pragma unroll
            for (int r = 0; r < RKHS; r++) {
                a0 = fmaf(k[r], w[0][r], a0);
                a1 = fmaf(k[r], w[1][r], a1);
                a2 = fmaf(k[r], w[2][r], a2);
                a3 = fmaf(k[r], w[3][r], a3);
            }
            res = make_float4(a0, a1, a2, a3);
        } else {
            float t = t_diff[row];
            res.x = cosf(fmaf(t, wf[0], bf[0]));
            res.y = cosf(fmaf(t, wf[1], bf[1]));
            res.z = cosf(fmaf(t, wf[2], bf[2]));
            res.w = cosf(fmaf(t, wf[3], bf[3]));
        }
        // out[row*128 + obase .. +3], coalesced float4 across the warp
        reinterpret_cast<float4*>(out)[row * (OUTD / 4) + lane] = res;
    }
}

extern "C" void kernel_launch(void* const* d_in, const int* in_sizes, int n_in,
                              void* d_out, int out_size)
{
    // metadata order: src, dst, t_diff, kde_idx, kde_mask, kde_table,
    //                 W_proj, b_proj, W_fb, b_fb
    const float* t_diff    = (const float*)d_in[2];
    const int*   kde_idx   = (const int*)d_in[3];
    const int*   kde_mask  = (const int*)d_in[4];
    const float* kde_table = (const float*)d_in[5];
    const float* W_proj    = (const float*)d_in[6];
    const float* b_proj    = (const float*)d_in[7];
    const float* W_fb      = (const float*)d_in[8];
    const float* b_fb      = (const float*)d_in[9];
    float*       out       = (float*)d_out;

    const int n = in_sizes[2];  // BATCH (t_diff element count)

    // 148 SMs * 8 blocks; 256 threads -> 9472 warps, grid-stride over 1M rows
    kde_time_encoder_kernel<<<1184, 256>>>(
        t_diff, kde_idx, kde_mask, kde_table, W_proj, b_proj, W_fb, b_fb, out, n);
}

// round 4
// speedup vs baseline: 2.0101x; 2.0101x over previous
#include <cuda_runtime.h>

#define RKHS 20
#define OUTD 128
#define TILE 128   // rows per tile == threads per block

// Tile-based two-phase kernel.
// Phase A: thread i stages row i's KDE vector (if masked) into smem.
//          Per-thread independent gathers -> up to 640 loads in flight/block.
// Phase B: thread = output column. Rows looped; k broadcast from smem,
//          w[20] per-column in registers. Mask is block-uniform per row.
__global__ __launch_bounds__(TILE) void kde_time_encoder_kernel(
    const float* __restrict__ t_diff,
    const int* __restrict__ kde_idx,
    const int* __restrict__ kde_mask,
    const float* __restrict__ kde_table,
    const float* __restrict__ W_proj,
    const float* __restrict__ b_proj,
    const float* __restrict__ W_fb,
    const float* __restrict__ b_fb,
    float* __restrict__ out,
    int n)
{
    __shared__ __align__(16) float sk[TILE * RKHS];  // 10 KB staged KDE vecs
    __shared__ float st[TILE];
    __shared__ int   sm[TILE];

    const int tid = threadIdx.x;   // == output column in phase B
    const int col = tid;

    // Hoist this column's weights into registers (row-invariant).
    float w[RKHS];
    {
        const float4* wrow = reinterpret_cast<const float4*>(W_proj + col * RKHS);
#pragma unroll
        for (int q = 0; q < 5; q++) {
            float4 v = wrow[q];
            w[q * 4 + 0] = v.x; w[q * 4 + 1] = v.y;
            w[q * 4 + 2] = v.z; w[q * 4 + 3] = v.w;
        }
    }
    const float bpv = b_proj[col];
    const float wfv = W_fb[col];
    const float bfv = b_fb[col];

    const int ntiles = (n + TILE - 1) / TILE;

    for (int tile = blockIdx.x; tile < ntiles; tile += gridDim.x) {
        const int base = tile * TILE;
        const int row  = base + tid;

        // ---- Phase A: stage this tile ----
        int   m  = 0;
        float tv = 0.0f;
        if (row < n) {
            m  = kde_mask[row];
            tv = t_diff[row];
        }
        sm[tid] = m;
        st[tid] = tv;
        if (m) {
            const float4* kv = reinterpret_cast<const float4*>(
                kde_table + (size_t)kde_idx[row] * RKHS);
            float4 v0 = kv[0], v1 = kv[1], v2 = kv[2], v3 = kv[3], v4 = kv[4];
            float4* dstp = reinterpret_cast<float4*>(sk + tid * RKHS);
            dstp[0] = v0; dstp[1] = v1; dstp[2] = v2; dstp[3] = v3; dstp[4] = v4;
        }
        __syncthreads();

        // ---- Phase B: compute tile, one column per thread ----
        const int nrows = min(TILE, n - base);
        float* outp = out + (size_t)base * OUTD + col;
        for (int r = 0; r < nrows; r++) {
            float res;
            if (sm[r]) {  // block-uniform branch
                const float4* kk = reinterpret_cast<const float4*>(sk + r * RKHS);
                float acc = bpv;
#pragma unroll
                for (int q = 0; q < 5; q++) {
                    float4 kv4 = kk[q];  // LDS.128 broadcast
                    acc = fmaf(kv4.x, w[q * 4 + 0], acc);
                    acc = fmaf(kv4.y, w[q * 4 + 1], acc);
                    acc = fmaf(kv4.z, w[q * 4 + 2], acc);
                    acc = fmaf(kv4.w, w[q * 4 + 3], acc);
                }
                res = acc;
            } else {
                res = cosf(fmaf(st[r], wfv, bfv));
            }
            __stcs(outp + (size_t)r * OUTD, res);  // streaming: don't thrash L2
        }
        __syncthreads();  // protect smem before next tile overwrites
    }
}

extern "C" void kernel_launch(void* const* d_in, const int* in_sizes, int n_in,
                              void* d_out, int out_size)
{
    // metadata order: src, dst, t_diff, kde_idx, kde_mask, kde_table,
    //                 W_proj, b_proj, W_fb, b_fb
    const float* t_diff    = (const float*)d_in[2];
    const int*   kde_idx   = (const int*)d_in[3];
    const int*   kde_mask  = (const int*)d_in[4];
    const float* kde_table = (const float*)d_in[5];
    const float* W_proj    = (const float*)d_in[6];
    const float* b_proj    = (const float*)d_in[7];
    const float* W_fb      = (const float*)d_in[8];
    const float* b_fb      = (const float*)d_in[9];
    float*       out       = (float*)d_out;

    const int n = in_sizes[2];  // BATCH

    // ~10-11 resident blocks/SM expected; grid-stride over 7813 tiles.
    kde_time_encoder_kernel<<<1536, TILE>>>(
        t_diff, kde_idx, kde_mask, kde_table, W_proj, b_proj, W_fb, b_fb, out, n);
}

// round 6
// speedup vs baseline: 3.5594x; 1.7707x over previous
#include <cuda_runtime.h>

#define RKHS 20
#define OUTD 128
#define TILE 128   // rows per tile == threads per block

// Fast cos for |arg| up to ~1e4: Cody-Waite 2-term reduction by 2*pi, then
// hardware MUFU cos on the reduced argument (|r| <= pi -> max err ~2^-21).
__device__ __forceinline__ float fast_cos(float x) {
    const float INV_2PI   = 0.15915494309189535f;
    const float TWO_PI_HI = 6.28318548202514648f;   // fp32(2*pi)
    const float TWO_PI_LO = -1.7484556e-7f;         // 2*pi - TWO_PI_HI
    float k = rintf(x * INV_2PI);
    float r = fmaf(-k, TWO_PI_HI, x);
    r = fmaf(-k, TWO_PI_LO, r);
    return __cosf(r);
}

// Two-phase tile kernel.
// Phase A: thread i stages row i's KDE vector (if masked) into smem
//          (independent per-thread gathers -> high MLP).
// Phase B: ONE WARP PER ROW. Lane l owns output cols [4l, 4l+4) with
//          w[4][20] hoisted to registers; k broadcast via LDS.128;
//          one STG.128 per lane per row.
__global__ __launch_bounds__(TILE, 4) void kde_time_encoder_kernel(
    const float* __restrict__ t_diff,
    const int* __restrict__ kde_idx,
    const int* __restrict__ kde_mask,
    const float* __restrict__ kde_table,
    const float* __restrict__ W_proj,
    const float* __restrict__ b_proj,
    const float* __restrict__ W_fb,
    const float* __restrict__ b_fb,
    float* __restrict__ out,
    int n)
{
    __shared__ __align__(16) float sk[TILE * RKHS];  // 10 KB staged KDE vecs
    __shared__ float st[TILE];
    __shared__ int   sm[TILE];

    const int tid  = threadIdx.x;
    const int lane = tid & 31;
    const int wid  = tid >> 5;        // 4 warps
    const int obase = lane * 4;       // this lane's 4 output columns

    // Hoist this lane's 4 weight rows (+biases) into registers.
    float w[4][RKHS];
    float bp[4], wf[4], bf[4];
#pragma unroll
    for (int j = 0; j < 4; j++) {
        const float4* wrow = reinterpret_cast<const float4*>(W_proj + (obase + j) * RKHS);
#pragma unroll
        for (int q = 0; q < 5; q++) {
            float4 v = wrow[q];
            w[j][q * 4 + 0] = v.x; w[j][q * 4 + 1] = v.y;
            w[j][q * 4 + 2] = v.z; w[j][q * 4 + 3] = v.w;
        }
        bp[j] = b_proj[obase + j];
        wf[j] = W_fb[obase + j];
        bf[j] = b_fb[obase + j];
    }

    const int ntiles = (n + TILE - 1) / TILE;

    for (int tile = blockIdx.x; tile < ntiles; tile += gridDim.x) {
        const int base = tile * TILE;
        const int row  = base + tid;

        // ---- Phase A: stage tile (coalesced meta loads, per-thread gathers) ----
        int   m  = 0;
        float tv = 0.0f;
        if (row < n) {
            m  = kde_mask[row];
            tv = t_diff[row];
        }
        sm[tid] = m;
        st[tid] = tv;
        if (m) {
            const float4* kv = reinterpret_cast<const float4*>(
                kde_table + (size_t)kde_idx[row] * RKHS);
            float4 v0 = kv[0], v1 = kv[1], v2 = kv[2], v3 = kv[3], v4 = kv[4];
            float4* dstp = reinterpret_cast<float4*>(sk + tid * RKHS);
            dstp[0] = v0; dstp[1] = v1; dstp[2] = v2; dstp[3] = v3; dstp[4] = v4;
        }
        __syncthreads();

        // ---- Phase B: warp per row; rows wid, wid+4, ... ----
        const int nrows = min(TILE, n - base);
        for (int r = wid; r < nrows; r += 4) {
            float4 res;
            if (sm[r]) {                       // warp-uniform branch
                const float4* kk = reinterpret_cast<const float4*>(sk + r * RKHS);
                float a0 = bp[0], a1 = bp[1], a2 = bp[2], a3 = bp[3];
#pragma unroll
                for (int q = 0; q < 5; q++) {
                    float4 kv4 = kk[q];        // LDS.128 broadcast
                    a0 = fmaf(kv4.x, w[0][q*4+0], a0);
                    a1 = fmaf(kv4.x, w[1][q*4+0], a1);
                    a2 = fmaf(kv4.x, w[2][q*4+0], a2);
                    a3 = fmaf(kv4.x, w[3][q*4+0], a3);
                    a0 = fmaf(kv4.y, w[0][q*4+1], a0);
                    a1 = fmaf(kv4.y, w[1][q*4+1], a1);
                    a2 = fmaf(kv4.y, w[2][q*4+1], a2);
                    a3 = fmaf(kv4.y, w[3][q*4+1], a3);
                    a0 = fmaf(kv4.z, w[0][q*4+2], a0);
                    a1 = fmaf(kv4.z, w[1][q*4+2], a1);
                    a2 = fmaf(kv4.z, w[2][q*4+2], a2);
                    a3 = fmaf(kv4.z, w[3][q*4+2], a3);
                    a0 = fmaf(kv4.w, w[0][q*4+3], a0);
                    a1 = fmaf(kv4.w, w[1][q*4+3], a1);
                    a2 = fmaf(kv4.w, w[2][q*4+3], a2);
                    a3 = fmaf(kv4.w, w[3][q*4+3], a3);
                }
                res = make_float4(a0, a1, a2, a3);
            } else {
                float t = st[r];
                res.x = fast_cos(fmaf(t, wf[0], bf[0]));
                res.y = fast_cos(fmaf(t, wf[1], bf[1]));
                res.z = fast_cos(fmaf(t, wf[2], bf[2]));
                res.w = fast_cos(fmaf(t, wf[3], bf[3]));
            }
            // One STG.128 per lane; warp covers the full 512B row.
            __stcs(reinterpret_cast<float4*>(out + (size_t)(base + r) * OUTD) + lane, res);
        }
        __syncthreads();  // protect smem before next tile overwrites
    }
}

extern "C" void kernel_launch(void* const* d_in, const int* in_sizes, int n_in,
                              void* d_out, int out_size)
{
    // metadata order: src, dst, t_diff, kde_idx, kde_mask, kde_table,
    //                 W_proj, b_proj, W_fb, b_fb
    const float* t_diff    = (const float*)d_in[2];
    const int*   kde_idx   = (const int*)d_in[3];
    const int*   kde_mask  = (const int*)d_in[4];
    const float* kde_table = (const float*)d_in[5];
    const float* W_proj    = (const float*)d_in[6];
    const float* b_proj    = (const float*)d_in[7];
    const float* W_fb      = (const float*)d_in[8];
    const float* b_fb      = (const float*)d_in[9];
    float*       out       = (float*)d_out;

    const int n = in_sizes[2];  // BATCH

    kde_time_encoder_kernel<<<1184, TILE>>>(
        t_diff, kde_idx, kde_mask, kde_table, W_proj, b_proj, W_fb, b_fb, out, n);
}